// round 15
// baseline (speedup 1.0000x reference)
#include <cuda_runtime.h>
#include <cuda_fp16.h>
#include <cstdint>

#define B_    64
#define S_    512
#define DIN   512
#define NCAP  32
#define DCAP  64
#define EPSQ  1e-7f

// ---------------- scratch (device globals; no allocations) ----------------
__device__ __half g_Uh[B_ * S_ * DIN];         // fp16 copy of U (converted once) ~34MB
__device__ float  g_Wt[NCAP * DCAP * DIN];     // W transposed: [n][d][i]
__device__ float  g_tp[4 * B_ * DIN];          // partial column sums of U
__device__ float  g_w[B_ * DIN * NCAP];        // w[b][i][n]
__device__ __half g_ch[B_ * S_ * NCAP];        // c[b][s][n] fp16 (post-softmax)
__device__ float  g_v[B_ * NCAP * DIN];        // v[b][n][i]

// ---------------- mma / ldmatrix helpers ----------------
__device__ __forceinline__ uint32_t h2u(__half2 h) {
    union { __half2 h; uint32_t u; } cvt;
    cvt.h = h;
    return cvt.u;
}
__device__ __forceinline__ void mma_f16(float& c0, float& c1, float& c2, float& c3,
                                        uint32_t a0, uint32_t a1, uint32_t a2, uint32_t a3,
                                        uint32_t b0, uint32_t b1) {
    asm("mma.sync.aligned.m16n8k16.row.col.f32.f16.f16.f32 "
        "{%0,%1,%2,%3}, {%4,%5,%6,%7}, {%8,%9}, {%0,%1,%2,%3};"
        : "+f"(c0), "+f"(c1), "+f"(c2), "+f"(c3)
        : "r"(a0), "r"(a1), "r"(a2), "r"(a3), "r"(b0), "r"(b1));
}
__device__ __forceinline__ uint32_t s2u(const void* p) {
    return (uint32_t)__cvta_generic_to_shared(p);
}
__device__ __forceinline__ void ldsm4(uint32_t& r0, uint32_t& r1, uint32_t& r2, uint32_t& r3,
                                      uint32_t addr) {
    asm volatile("ldmatrix.sync.aligned.m8n8.x4.shared.b16 {%0,%1,%2,%3}, [%4];"
                 : "=r"(r0), "=r"(r1), "=r"(r2), "=r"(r3) : "r"(addr));
}
__device__ __forceinline__ void ldsm4t(uint32_t& r0, uint32_t& r1, uint32_t& r2, uint32_t& r3,
                                       uint32_t addr) {
    asm volatile("ldmatrix.sync.aligned.m8n8.x4.trans.shared.b16 {%0,%1,%2,%3}, [%4];"
                 : "=r"(r0), "=r"(r1), "=r"(r2), "=r"(r3) : "r"(addr));
}

// ---------------- prep: blocks 0..255 transpose W; 256..511 colsum U + fp16 convert ----
__global__ __launch_bounds__(256) void prep_k(const float* __restrict__ U,
                                              const float* __restrict__ W) {
    int t = threadIdx.x;
    if (blockIdx.x < 256) {
        int n  = blockIdx.x >> 3;
        int i0 = (blockIdx.x & 7) * 64;
        __shared__ float sm[64 * 65];
        #pragma unroll
        for (int r = 0; r < 16; ++r) {
            int idx = r * 256 + t;
            int d = idx & 63, ii = idx >> 6;
            sm[d * 65 + ii] = W[(size_t)(i0 + ii) * 2048 + n * 64 + d];
        }
        __syncthreads();
        #pragma unroll
        for (int r = 0; r < 16; ++r) {
            int idx = r * 256 + t;
            int ii = idx & 63, d = idx >> 6;
            g_Wt[((size_t)n * 64 + d) * 512 + i0 + ii] = sm[d * 65 + ii];
        }
    } else {
        int idx = blockIdx.x - 256;
        int b = idx & 63, sc = idx >> 6;
        size_t base = ((size_t)b * S_ + sc * 128) * DIN;
        const float2* p = (const float2*)(U + base) + t;
        __half2* qh = (__half2*)(g_Uh + base) + t;
        float2 a = make_float2(0.f, 0.f);
        #pragma unroll 4
        for (int s = 0; s < 128; ++s) {
            float2 f = p[(size_t)s * 256];
            a.x += f.x; a.y += f.y;
            qh[(size_t)s * 256] = __floats2half2_rn(f.x, f.y);
        }
        *(float2*)(g_tp + ((size_t)sc * B_ + b) * DIN + t * 2) = a;
    }
}

// ---------------- fused out + w (fp32, unchanged) ----------------
__global__ __launch_bounds__(512) void outw_k(float* __restrict__ out, int bcast, int dow) {
    int n  = blockIdx.x;
    int b0 = blockIdx.y * 8;
    __shared__ __align__(16) float sv[8][DIN];
    __shared__ float so[8][DCAP];
    int t = threadIdx.x, w = t >> 5, lane = t & 31;
    const float* Wn = g_Wt + (size_t)n * DCAP * DIN;

    #pragma unroll
    for (int r = 0; r < 8; ++r) {
        int idx = r * 512 + t;
        int bb = idx >> 9, pos = idx & 511;
        int b = b0 + bb;
        float val;
        if (bcast)
            val = g_tp[(size_t)b * DIN + pos]
                + g_tp[((size_t)B_ + b) * DIN + pos]
                + g_tp[((size_t)2 * B_ + b) * DIN + pos]
                + g_tp[((size_t)3 * B_ + b) * DIN + pos];
        else
            val = g_v[((size_t)b * NCAP + n) * DIN + pos];
        sv[bb][pos] = val;
    }
    __syncthreads();

    #pragma unroll
    for (int r = 0; r < 4; ++r) {
        int d = r * 16 + w;
        const float4* wp = (const float4*)(Wn + (size_t)d * DIN);
        float acc[8] = {};
        #pragma unroll
        for (int q = 0; q < 4; ++q) {
            float4 wv = wp[lane + q * 32];
            #pragma unroll
            for (int bb = 0; bb < 8; ++bb) {
                float4 vv = ((const float4*)sv[bb])[lane + q * 32];
                acc[bb] += wv.x * vv.x + wv.y * vv.y + wv.z * vv.z + wv.w * vv.w;
            }
        }
        #pragma unroll
        for (int bb = 0; bb < 8; ++bb) {
            #pragma unroll
            for (int off = 16; off; off >>= 1)
                acc[bb] += __shfl_xor_sync(0xffffffffu, acc[bb], off);
        }
        if (lane == 0) {
            #pragma unroll
            for (int bb = 0; bb < 8; ++bb) so[bb][d] = acc[bb];
        }
    }
    __syncthreads();

    if (w < 8) {
        int b = b0 + w;
        float o1 = so[w][lane], o2 = so[w][lane + 32];
        if (bcast) { o1 *= (1.f / 32.f); o2 *= (1.f / 32.f); }
        float sq = o1 * o1 + o2 * o2;
        #pragma unroll
        for (int off = 16; off; off >>= 1) sq += __shfl_xor_sync(0xffffffffu, sq, off);
        float rn = rsqrtf(sq + EPSQ);
        o1 *= rn; o2 *= rn;
        out[((size_t)b * NCAP + n) * DCAP + lane]      = o1;
        out[((size_t)b * NCAP + n) * DCAP + lane + 32] = o2;
        so[w][lane]      = o1;
        so[w][lane + 32] = o2;
    }
    __syncthreads();

    if (dow) {
        int i = t;
        float acc[8] = {};
        #pragma unroll 8
        for (int d = 0; d < DCAP; ++d) {
            float wt = Wn[(size_t)d * DIN + i];
            #pragma unroll
            for (int bb = 0; bb < 8; ++bb) acc[bb] += so[bb][d] * wt;
        }
        #pragma unroll
        for (int bb = 0; bb < 8; ++bb)
            g_w[((size_t)(b0 + bb) * DIN + i) * NCAP + n] = acc[bb];
    }
}

// ---------------- fp16 MMA: logits[s,n] = U[s,:]·w[:,n], softmax fused ----------------
// grid (4 s-tiles, 64 b), block 256 (8 warps). Tile 128s x 32n; warp = 16s x 32n.
// B (w, fp16) staged ONCE in smem (one syncthreads); mainloop is warp-autonomous:
// per-warp double-buffered A staging, __syncwarp only.
// dyn smem: [0, 40960) B = 512x40 halfs; [40960, 61440) A = 8 warps x 2 bufs x 16x40 halfs.
__global__ __launch_bounds__(256) void blogmma_k() {
    extern __shared__ __align__(16) char dsm[];
    __half* sB = (__half*)dsm;
    int t = threadIdx.x, w = t >> 5, lane = t & 31;
    __half* sAw = (__half*)(dsm + 40960) + w * 1280;   // 2 bufs x 640 halfs
    int g = lane >> 2, tg = lane & 3;
    int wrow = w * 16;
    int s0 = blockIdx.x * 128;
    int b  = blockIdx.y;
    const __half* Ub = g_Uh + ((size_t)b * S_ + s0) * DIN;
    int arow = (lane & 7) + ((lane >> 3) & 1) * 8, acol = (lane >> 4) * 8;  // A non-trans
    int brow = arow, bcol = acol;                                           // B trans

    // ---- stage B (whole w block, fp32 -> fp16) ----
    {
        const float4* wb4 = (const float4*)(g_w + (size_t)b * DIN * NCAP);
        #pragma unroll
        for (int j = 0; j < 16; ++j) {
            int f = t + j * 256;             // 4096 float4
            int row = f >> 3, part = f & 7;
            float4 v = wb4[f];
            *(__half2*)&sB[row * 40 + part * 4]     = __floats2half2_rn(v.x, v.y);
            *(__half2*)&sB[row * 40 + part * 4 + 2] = __floats2half2_rn(v.z, v.w);
        }
    }
    // ---- per-warp A prologue: stage chunk0, prefetch chunk1 ----
    int r = lane >> 1, pb = (lane & 1) * 16;
    const __half* Arow = Ub + (size_t)(wrow + r) * DIN;
    uint4 pu[2];
    pu[0] = *(const uint4*)(Arow + pb);
    pu[1] = *(const uint4*)(Arow + pb + 8);
    *(uint4*)&sAw[r * 40 + pb]     = pu[0];
    *(uint4*)&sAw[r * 40 + pb + 8] = pu[1];
    pu[0] = *(const uint4*)(Arow + 32 + pb);
    pu[1] = *(const uint4*)(Arow + 32 + pb + 8);
    __syncthreads();   // B + all A buf0 visible

    float c[4][4] = {};
    #pragma unroll 1
    for (int ch = 0; ch < 16; ++ch) {
        int cur = ch & 1, nxt = cur ^ 1;
        if (ch < 15) {
            __half* sn = sAw + nxt * 640;
            *(uint4*)&sn[r * 40 + pb]     = pu[0];
            *(uint4*)&sn[r * 40 + pb + 8] = pu[1];
        }
        if (ch < 14) {
            int k0 = (ch + 2) * 32;
            pu[0] = *(const uint4*)(Arow + k0 + pb);
            pu[1] = *(const uint4*)(Arow + k0 + pb + 8);
        }
        __syncwarp();
        __half* sa = sAw + cur * 640;
        #pragma unroll
        for (int ks = 0; ks < 32; ks += 16) {
            uint32_t a[4], bb2[2][4];
            ldsm4(a[0], a[1], a[2], a[3], s2u(&sa[arow * 40 + ks + acol]));
            #pragma unroll
            for (int np = 0; np < 2; ++np)
                ldsm4t(bb2[np][0], bb2[np][1], bb2[np][2], bb2[np][3],
                       s2u(&sB[(ch * 32 + ks + brow) * 40 + np * 16 + bcol]));
            #pragma unroll
            for (int np = 0; np < 2; ++np) {
                mma_f16(c[2 * np][0], c[2 * np][1], c[2 * np][2], c[2 * np][3],
                        a[0], a[1], a[2], a[3], bb2[np][0], bb2[np][1]);
                mma_f16(c[2 * np + 1][0], c[2 * np + 1][1], c[2 * np + 1][2], c[2 * np + 1][3],
                        a[0], a[1], a[2], a[3], bb2[np][2], bb2[np][3]);
            }
        }
        __syncwarp();
    }
    // softmax over n per s-row; fp16 store (no block sync needed)
    __half* cbase = g_ch + ((size_t)b * S_ + s0) * NCAP;
    #pragma unroll
    for (int half = 0; half < 2; ++half) {
        int row = wrow + g + half * 8;
        float v0 = c[0][half * 2], v1 = c[0][half * 2 + 1];
        float v2 = c[1][half * 2], v3 = c[1][half * 2 + 1];
        float v4 = c[2][half * 2], v5 = c[2][half * 2 + 1];
        float v6 = c[3][half * 2], v7 = c[3][half * 2 + 1];
        float m = fmaxf(fmaxf(fmaxf(v0, v1), fmaxf(v2, v3)),
                        fmaxf(fmaxf(v4, v5), fmaxf(v6, v7)));
        m = fmaxf(m, __shfl_xor_sync(0xffffffffu, m, 1));
        m = fmaxf(m, __shfl_xor_sync(0xffffffffu, m, 2));
        float e0 = __expf(v0 - m), e1 = __expf(v1 - m), e2 = __expf(v2 - m), e3 = __expf(v3 - m);
        float e4 = __expf(v4 - m), e5 = __expf(v5 - m), e6 = __expf(v6 - m), e7 = __expf(v7 - m);
        float sm = e0 + e1 + e2 + e3 + e4 + e5 + e6 + e7;
        sm += __shfl_xor_sync(0xffffffffu, sm, 1);
        sm += __shfl_xor_sync(0xffffffffu, sm, 2);
        float inv = 1.f / sm;
        __half2* cr = (__half2*)(cbase + (size_t)row * NCAP + 2 * tg);
        cr[0]  = __floats2half2_rn(e0 * inv, e1 * inv);
        cr[4]  = __floats2half2_rn(e2 * inv, e3 * inv);
        cr[8]  = __floats2half2_rn(e4 * inv, e5 * inv);
        cr[12] = __floats2half2_rn(e6 * inv, e7 * inv);
    }
}

// ---------------- fp16 MMA: v[n,i] = sum_s c[s,n] U[s,i] (v^T then transpose) ----------
// grid (4 i-tiles, 64 b), block 256 (8 warps). Tile 128i x 32n; warp = 16i x 32n.
// B (c, fp16) staged once; warp-autonomous mainloop.
// dyn smem: [0, 40960) B = 512x40 halfs; [40960, 65536) A = 8 x 2 x 32x24 halfs
//           (A region reused as vsm 128x33 floats in the epilogue).
__global__ __launch_bounds__(256) void vmma_k() {
    extern __shared__ __align__(16) char dsm[];
    __half* sB = (__half*)dsm;
    int t = threadIdx.x, w = t >> 5, lane = t & 31;
    __half* sAw = (__half*)(dsm + 40960) + w * 1536;   // 2 bufs x 768 halfs (32x24)
    float* vsm = (float*)(dsm + 40960);
    int g = lane >> 2, tg = lane & 3;
    int wi = w * 16;
    int i0 = blockIdx.x * 128;
    int b  = blockIdx.y;
    const __half* Ub = g_Uh + (size_t)b * S_ * DIN;
    const __half* cb = g_ch + (size_t)b * S_ * NCAP;
    int tarow = (lane & 7) + ((lane >> 4) & 1) * 8, tacol = ((lane >> 3) & 1) * 8;  // A trans
    int tbrow = (lane & 7) + ((lane >> 3) & 1) * 8, tbcol = (lane >> 4) * 8;        // B trans

    // ---- stage B (whole c block, already fp16) ----
    {
        const uint4* cb4 = (const uint4*)cb;   // 2048 uint4
        #pragma unroll
        for (int j = 0; j < 8; ++j) {
            int f = t + j * 256;
            int row = f >> 2, part = f & 3;
            *(uint4*)&sB[row * 40 + part * 8] = cb4[f];
        }
    }
    // ---- per-warp A prologue: stage chunk0 (s 0..31), prefetch chunk1 ----
    const __half* Acol = Ub + (size_t)lane * DIN + i0 + wi;   // row = s (lane), 16 i halfs
    uint4 pu[2];
    pu[0] = *(const uint4*)(Acol);
    pu[1] = *(const uint4*)(Acol + 8);
    *(uint4*)&sAw[lane * 24]     = pu[0];
    *(uint4*)&sAw[lane * 24 + 8] = pu[1];
    pu[0] = *(const uint4*)(Acol + (size_t)32 * DIN);
    pu[1] = *(const uint4*)(Acol + (size_t)32 * DIN + 8);
    __syncthreads();

    float c[4][4] = {};
    #pragma unroll 1
    for (int ch = 0; ch < 16; ++ch) {
        int cur = ch & 1, nxt = cur ^ 1;
        if (ch < 15) {
            __half* sn = sAw + nxt * 768;
            *(uint4*)&sn[lane * 24]     = pu[0];
            *(uint4*)&sn[lane * 24 + 8] = pu[1];
        }
        if (ch < 14) {
            size_t soff = (size_t)(ch + 2) * 32 * DIN;
            pu[0] = *(const uint4*)(Acol + soff);
            pu[1] = *(const uint4*)(Acol + soff + 8);
        }
        __syncwarp();
        __half* sa = sAw + cur * 768;
        #pragma unroll
        for (int ks = 0; ks < 32; ks += 16) {
            uint32_t a[4], bb2[2][4];
            ldsm4t(a[0], a[1], a[2], a[3], s2u(&sa[(ks + tarow) * 24 + tacol]));
            #pragma unroll
            for (int np = 0; np < 2; ++np)
                ldsm4t(bb2[np][0], bb2[np][1], bb2[np][2], bb2[np][3],
                       s2u(&sB[(ch * 32 + ks + tbrow) * 40 + np * 16 + tbcol]));
            #pragma unroll
            for (int np = 0; np < 2; ++np) {
                mma_f16(c[2 * np][0], c[2 * np][1], c[2 * np][2], c[2 * np][3],
                        a[0], a[1], a[2], a[3], bb2[np][0], bb2[np][1]);
                mma_f16(c[2 * np + 1][0], c[2 * np + 1][1], c[2 * np + 1][2], c[2 * np + 1][3],
                        a[0], a[1], a[2], a[3], bb2[np][2], bb2[np][3]);
            }
        }
        __syncwarp();
    }
    // transpose v^T[i][n] -> v[n][i] via smem (reuses A region), coalesced store
    __syncthreads();
    #pragma unroll
    for (int nt = 0; nt < 4; ++nt) {
        int nc = nt * 8 + 2 * tg;
        vsm[(wi + g)     * 33 + nc]     = c[nt][0];
        vsm[(wi + g)     * 33 + nc + 1] = c[nt][1];
        vsm[(wi + g + 8) * 33 + nc]     = c[nt][2];
        vsm[(wi + g + 8) * 33 + nc + 1] = c[nt][3];
    }
    __syncthreads();
    {
        int n = t >> 3, igrp = t & 7;
        float* vb = g_v + ((size_t)b * NCAP + n) * DIN + i0;
        #pragma unroll
        for (int q = 0; q < 4; ++q) {
            int i4 = igrp * 4 + q * 32;
            float4 o = make_float4(vsm[(i4 + 0) * 33 + n], vsm[(i4 + 1) * 33 + n],
                                   vsm[(i4 + 2) * 33 + n], vsm[(i4 + 3) * 33 + n]);
            *(float4*)(vb + i4) = o;
        }
    }
}

// ---------------- launch ----------------
extern "C" void kernel_launch(void* const* d_in, const int* in_sizes, int n_in,
                              void* d_out, int out_size) {
    const float* U = (const float*)d_in[0];   // (64, 512, 512)
    const float* W = (const float*)d_in[1];   // (512, 2048)
    float* out = (float*)d_out;               // (64, 32, 64)

    cudaFuncSetAttribute(blogmma_k, cudaFuncAttributeMaxDynamicSharedMemorySize, 61440);
    cudaFuncSetAttribute(vmma_k,    cudaFuncAttributeMaxDynamicSharedMemorySize, 65536);

    prep_k<<<512, 256>>>(U, W);
    outw_k<<<dim3(32, 8), 512>>>(out, 1, 1);                   // iteration 0 + w0
    for (int it = 0; it < 2; ++it) {
        blogmma_k<<<dim3(4, 64), 256, 61440>>>();
        vmma_k<<<dim3(4, 64), 256, 65536>>>();
        outw_k<<<dim3(32, 8), 512>>>(out, 0, it == 0);         // out + (w for iter 1 only)
    }
}

// round 16
// speedup vs baseline: 1.1200x; 1.1200x over previous
#include <cuda_runtime.h>
#include <cuda_fp16.h>
#include <cstdint>

#define B_    64
#define S_    512
#define DIN   512
#define NCAP  32
#define DCAP  64
#define EPSQ  1e-7f

// ---------------- scratch (device globals; no allocations) ----------------
__device__ __half g_Uh[B_ * S_ * DIN];         // fp16 copy of U (converted once) ~34MB
__device__ float  g_Wt[NCAP * DCAP * DIN];     // W transposed: [n][d][i]
__device__ float  g_tp[4 * B_ * DIN];          // partial column sums of U
__device__ __half g_wh[B_ * DIN * NCAP];       // w[b][i][n] fp16
__device__ __half g_ch[B_ * S_ * NCAP];        // c[b][s][n] fp16 (post-softmax)
__device__ float  g_v[B_ * NCAP * DIN];        // v[b][n][i]

// ---------------- mma / ldmatrix / cp.async helpers ----------------
__device__ __forceinline__ void mma_f16(float& c0, float& c1, float& c2, float& c3,
                                        uint32_t a0, uint32_t a1, uint32_t a2, uint32_t a3,
                                        uint32_t b0, uint32_t b1) {
    asm("mma.sync.aligned.m16n8k16.row.col.f32.f16.f16.f32 "
        "{%0,%1,%2,%3}, {%4,%5,%6,%7}, {%8,%9}, {%0,%1,%2,%3};"
        : "+f"(c0), "+f"(c1), "+f"(c2), "+f"(c3)
        : "r"(a0), "r"(a1), "r"(a2), "r"(a3), "r"(b0), "r"(b1));
}
__device__ __forceinline__ uint32_t s2u(const void* p) {
    return (uint32_t)__cvta_generic_to_shared(p);
}
__device__ __forceinline__ void ldsm4(uint32_t& r0, uint32_t& r1, uint32_t& r2, uint32_t& r3,
                                      uint32_t addr) {
    asm volatile("ldmatrix.sync.aligned.m8n8.x4.shared.b16 {%0,%1,%2,%3}, [%4];"
                 : "=r"(r0), "=r"(r1), "=r"(r2), "=r"(r3) : "r"(addr));
}
__device__ __forceinline__ void ldsm4t(uint32_t& r0, uint32_t& r1, uint32_t& r2, uint32_t& r3,
                                       uint32_t addr) {
    asm volatile("ldmatrix.sync.aligned.m8n8.x4.trans.shared.b16 {%0,%1,%2,%3}, [%4];"
                 : "=r"(r0), "=r"(r1), "=r"(r2), "=r"(r3) : "r"(addr));
}
__device__ __forceinline__ void cp16(uint32_t dst, const void* src) {
    asm volatile("cp.async.cg.shared.global [%0], [%1], 16;" :: "r"(dst), "l"(src));
}
__device__ __forceinline__ void cp_commit() {
    asm volatile("cp.async.commit_group;");
}
template <int N>
__device__ __forceinline__ void cp_wait() {
    asm volatile("cp.async.wait_group %0;" :: "n"(N));
}

// ---------------- prep: blocks 0..255 transpose W; 256..511 colsum U + fp16 convert ----
__global__ __launch_bounds__(256) void prep_k(const float* __restrict__ U,
                                              const float* __restrict__ W) {
    int t = threadIdx.x;
    if (blockIdx.x < 256) {
        int n  = blockIdx.x >> 3;
        int i0 = (blockIdx.x & 7) * 64;
        __shared__ float sm[64 * 65];
        #pragma unroll
        for (int r = 0; r < 16; ++r) {
            int idx = r * 256 + t;
            int d = idx & 63, ii = idx >> 6;
            sm[d * 65 + ii] = W[(size_t)(i0 + ii) * 2048 + n * 64 + d];
        }
        __syncthreads();
        #pragma unroll
        for (int r = 0; r < 16; ++r) {
            int idx = r * 256 + t;
            int ii = idx & 63, d = idx >> 6;
            g_Wt[((size_t)n * 64 + d) * 512 + i0 + ii] = sm[d * 65 + ii];
        }
    } else {
        int idx = blockIdx.x - 256;
        int b = idx & 63, sc = idx >> 6;
        size_t base = ((size_t)b * S_ + sc * 128) * DIN;
        const float2* p = (const float2*)(U + base) + t;
        __half2* qh = (__half2*)(g_Uh + base) + t;
        float2 a = make_float2(0.f, 0.f);
        #pragma unroll 4
        for (int s = 0; s < 128; ++s) {
            float2 f = p[(size_t)s * 256];
            a.x += f.x; a.y += f.y;
            qh[(size_t)s * 256] = __floats2half2_rn(f.x, f.y);
        }
        *(float2*)(g_tp + ((size_t)sc * B_ + b) * DIN + t * 2) = a;
    }
}

// ---------------- fused out + w (fp32 compute; w stored fp16) ----------------
__global__ __launch_bounds__(512) void outw_k(float* __restrict__ out, int bcast, int dow) {
    int n  = blockIdx.x;
    int b0 = blockIdx.y * 8;
    __shared__ __align__(16) float sv[8][DIN];
    __shared__ float so[8][DCAP];
    int t = threadIdx.x, w = t >> 5, lane = t & 31;
    const float* Wn = g_Wt + (size_t)n * DCAP * DIN;

    #pragma unroll
    for (int r = 0; r < 8; ++r) {
        int idx = r * 512 + t;
        int bb = idx >> 9, pos = idx & 511;
        int b = b0 + bb;
        float val;
        if (bcast)
            val = g_tp[(size_t)b * DIN + pos]
                + g_tp[((size_t)B_ + b) * DIN + pos]
                + g_tp[((size_t)2 * B_ + b) * DIN + pos]
                + g_tp[((size_t)3 * B_ + b) * DIN + pos];
        else
            val = g_v[((size_t)b * NCAP + n) * DIN + pos];
        sv[bb][pos] = val;
    }
    __syncthreads();

    #pragma unroll
    for (int r = 0; r < 4; ++r) {
        int d = r * 16 + w;
        const float4* wp = (const float4*)(Wn + (size_t)d * DIN);
        float acc[8] = {};
        #pragma unroll
        for (int q = 0; q < 4; ++q) {
            float4 wv = wp[lane + q * 32];
            #pragma unroll
            for (int bb = 0; bb < 8; ++bb) {
                float4 vv = ((const float4*)sv[bb])[lane + q * 32];
                acc[bb] += wv.x * vv.x + wv.y * vv.y + wv.z * vv.z + wv.w * vv.w;
            }
        }
        #pragma unroll
        for (int bb = 0; bb < 8; ++bb) {
            #pragma unroll
            for (int off = 16; off; off >>= 1)
                acc[bb] += __shfl_xor_sync(0xffffffffu, acc[bb], off);
        }
        if (lane == 0) {
            #pragma unroll
            for (int bb = 0; bb < 8; ++bb) so[bb][d] = acc[bb];
        }
    }
    __syncthreads();

    if (w < 8) {
        int b = b0 + w;
        float o1 = so[w][lane], o2 = so[w][lane + 32];
        if (bcast) { o1 *= (1.f / 32.f); o2 *= (1.f / 32.f); }
        float sq = o1 * o1 + o2 * o2;
        #pragma unroll
        for (int off = 16; off; off >>= 1) sq += __shfl_xor_sync(0xffffffffu, sq, off);
        float rn = rsqrtf(sq + EPSQ);
        o1 *= rn; o2 *= rn;
        out[((size_t)b * NCAP + n) * DCAP + lane]      = o1;
        out[((size_t)b * NCAP + n) * DCAP + lane + 32] = o2;
        so[w][lane]      = o1;
        so[w][lane + 32] = o2;
    }
    __syncthreads();

    if (dow) {
        int i = t;
        float acc[8] = {};
        #pragma unroll 8
        for (int d = 0; d < DCAP; ++d) {
            float wt = Wn[(size_t)d * DIN + i];
            #pragma unroll
            for (int bb = 0; bb < 8; ++bb) acc[bb] += so[bb][d] * wt;
        }
        #pragma unroll
        for (int bb = 0; bb < 8; ++bb)
            g_wh[((size_t)(b0 + bb) * DIN + i) * NCAP + n] = __float2half_rn(acc[bb]);
    }
}

// ---------------- fp16 MMA: logits[s,n] = U[s,:]·w[:,n], softmax fused ----------------
// grid (4 s-tiles, 64 b), block 256 (8 warps). Tile 128s x 32n; warp = 16s x 32n.
// cp.async staging, 3-stage ring, ONE syncthreads per 32-k chunk.
// dyn smem: su 3 x 128x40 halfs (30720B), sw 3 x 32x40 halfs (7680B) = 38400B.
__global__ __launch_bounds__(256) void blogmma_k() {
    extern __shared__ __align__(16) char dsm[];
    __half* suB = (__half*)dsm;                    // buf stride 5120 halfs
    __half* swB = (__half*)(dsm + 30720);          // buf stride 1280 halfs
    int t = threadIdx.x, w = t >> 5, lane = t & 31;
    int g = lane >> 2, tg = lane & 3;
    int wrow = w * 16;
    int s0 = blockIdx.x * 128;
    int b  = blockIdx.y;
    const __half* Ub  = g_Uh + ((size_t)b * S_ + s0) * DIN;
    const __half* whb = g_wh + (size_t)b * DIN * NCAP;
    int arow = (lane & 7) + ((lane >> 3) & 1) * 8, acol = (lane >> 4) * 8;
    int brow = arow, bcol = acol;
    // loader coords
    int ur = t >> 2, uq = t & 3;        // su: rows via 2 passes (f>>2, f&3)
    int wr = (t & 127) >> 2, wq = t & 3;
    bool wl = (t < 128);

    #define BLOG_ISSUE(CH) do {                                                   \
        int _k0 = (CH) * 32;                                                      \
        __half* _sd = suB + ((CH) % 3) * 5120;                                    \
        cp16(s2u(&_sd[ur * 40 + uq * 8]), Ub + (size_t)ur * DIN + _k0 + uq * 8);  \
        cp16(s2u(&_sd[(ur + 64) * 40 + uq * 8]),                                  \
             Ub + (size_t)(ur + 64) * DIN + _k0 + uq * 8);                        \
        if (wl) {                                                                 \
            __half* _sw = swB + ((CH) % 3) * 1280;                                \
            cp16(s2u(&_sw[wr * 40 + wq * 8]),                                     \
                 whb + (size_t)(_k0 + wr) * NCAP + wq * 8);                       \
        }                                                                         \
        cp_commit();                                                              \
    } while (0)

    BLOG_ISSUE(0);
    BLOG_ISSUE(1);

    float c[4][4] = {};
    #pragma unroll 1
    for (int ch = 0; ch < 16; ++ch) {
        if (ch < 14) cp_wait<1>(); else cp_wait<0>();
        __syncthreads();
        if (ch < 14) BLOG_ISSUE(ch + 2);
        __half* sa = suB + (ch % 3) * 5120;
        __half* sw = swB + (ch % 3) * 1280;
        #pragma unroll
        for (int ks = 0; ks < 32; ks += 16) {
            uint32_t a[4], bb2[2][4];
            ldsm4(a[0], a[1], a[2], a[3], s2u(&sa[(wrow + arow) * 40 + ks + acol]));
            #pragma unroll
            for (int np = 0; np < 2; ++np)
                ldsm4t(bb2[np][0], bb2[np][1], bb2[np][2], bb2[np][3],
                       s2u(&sw[(ks + brow) * 40 + np * 16 + bcol]));
            #pragma unroll
            for (int np = 0; np < 2; ++np) {
                mma_f16(c[2 * np][0], c[2 * np][1], c[2 * np][2], c[2 * np][3],
                        a[0], a[1], a[2], a[3], bb2[np][0], bb2[np][1]);
                mma_f16(c[2 * np + 1][0], c[2 * np + 1][1], c[2 * np + 1][2], c[2 * np + 1][3],
                        a[0], a[1], a[2], a[3], bb2[np][2], bb2[np][3]);
            }
        }
    }
    #undef BLOG_ISSUE
    // softmax over n per s-row (row's 32 n on 4 lanes sharing g: xor 1,2); fp16 store
    __half* cbase = g_ch + ((size_t)b * S_ + s0) * NCAP;
    #pragma unroll
    for (int half = 0; half < 2; ++half) {
        int row = wrow + g + half * 8;
        float v0 = c[0][half * 2], v1 = c[0][half * 2 + 1];
        float v2 = c[1][half * 2], v3 = c[1][half * 2 + 1];
        float v4 = c[2][half * 2], v5 = c[2][half * 2 + 1];
        float v6 = c[3][half * 2], v7 = c[3][half * 2 + 1];
        float m = fmaxf(fmaxf(fmaxf(v0, v1), fmaxf(v2, v3)),
                        fmaxf(fmaxf(v4, v5), fmaxf(v6, v7)));
        m = fmaxf(m, __shfl_xor_sync(0xffffffffu, m, 1));
        m = fmaxf(m, __shfl_xor_sync(0xffffffffu, m, 2));
        float e0 = __expf(v0 - m), e1 = __expf(v1 - m), e2 = __expf(v2 - m), e3 = __expf(v3 - m);
        float e4 = __expf(v4 - m), e5 = __expf(v5 - m), e6 = __expf(v6 - m), e7 = __expf(v7 - m);
        float sm = e0 + e1 + e2 + e3 + e4 + e5 + e6 + e7;
        sm += __shfl_xor_sync(0xffffffffu, sm, 1);
        sm += __shfl_xor_sync(0xffffffffu, sm, 2);
        float inv = 1.f / sm;
        __half2* cr = (__half2*)(cbase + (size_t)row * NCAP + 2 * tg);
        cr[0]  = __floats2half2_rn(e0 * inv, e1 * inv);
        cr[4]  = __floats2half2_rn(e2 * inv, e3 * inv);
        cr[8]  = __floats2half2_rn(e4 * inv, e5 * inv);
        cr[12] = __floats2half2_rn(e6 * inv, e7 * inv);
    }
}

// ---------------- fp16 MMA: v[n,i] = sum_s c[s,n] U[s,i] (v^T then transpose) ----------
// grid (4 i-tiles, 64 b), block 256 (8 warps). Tile 128i x 32n; warp = 16i x 32n.
// cp.async staging, 3-stage ring, one syncthreads per 32-s chunk.
// dyn smem: su 3 x 32x136 halfs (26112B), sc 3 x 32x40 halfs (7680B) = 33792B.
// Epilogue reuses [0, 16896) as vsm 128x33 floats.
__global__ __launch_bounds__(256) void vmma_k() {
    extern __shared__ __align__(16) char dsm[];
    __half* suB = (__half*)dsm;                    // buf stride 4352 halfs
    __half* scB = (__half*)(dsm + 26112);          // buf stride 1280 halfs
    float*  vsm = (float*)dsm;
    int t = threadIdx.x, w = t >> 5, lane = t & 31;
    int g = lane >> 2, tg = lane & 3;
    int wi = w * 16;
    int i0 = blockIdx.x * 128;
    int b  = blockIdx.y;
    const __half* Ub = g_Uh + (size_t)b * S_ * DIN;
    const __half* cb = g_ch + (size_t)b * S_ * NCAP;
    int tarow = (lane & 7) + ((lane >> 4) & 1) * 8, tacol = ((lane >> 3) & 1) * 8;
    int tbrow = (lane & 7) + ((lane >> 3) & 1) * 8, tbcol = (lane >> 4) * 8;
    // loader coords
    int ur = t >> 4, uq = t & 15;       // su rows (2 passes: ur, ur+16)
    int cr_ = (t & 127) >> 2, cq = t & 3;
    bool cl = (t < 128);

    #define VMMA_ISSUE(CH) do {                                                    \
        int _s1 = (CH) * 32;                                                       \
        __half* _sd = suB + ((CH) % 3) * 4352;                                     \
        cp16(s2u(&_sd[ur * 136 + uq * 8]),                                         \
             Ub + (size_t)(_s1 + ur) * DIN + i0 + uq * 8);                         \
        cp16(s2u(&_sd[(ur + 16) * 136 + uq * 8]),                                  \
             Ub + (size_t)(_s1 + ur + 16) * DIN + i0 + uq * 8);                    \
        if (cl) {                                                                  \
            __half* _sc = scB + ((CH) % 3) * 1280;                                 \
            cp16(s2u(&_sc[cr_ * 40 + cq * 8]),                                     \
                 cb + (size_t)(_s1 + cr_) * NCAP + cq * 8);                        \
        }                                                                          \
        cp_commit();                                                               \
    } while (0)

    VMMA_ISSUE(0);
    VMMA_ISSUE(1);

    float c[4][4] = {};
    #pragma unroll 1
    for (int ch = 0; ch < 16; ++ch) {
        if (ch < 14) cp_wait<1>(); else cp_wait<0>();
        __syncthreads();
        if (ch < 14) VMMA_ISSUE(ch + 2);
        __half* sa = suB + (ch % 3) * 4352;
        __half* sc = scB + (ch % 3) * 1280;
        #pragma unroll
        for (int ks = 0; ks < 32; ks += 16) {
            uint32_t a[4], bb2[2][4];
            ldsm4t(a[0], a[1], a[2], a[3],
                   s2u(&sa[(ks + tarow) * 136 + wi + tacol]));
            #pragma unroll
            for (int np = 0; np < 2; ++np)
                ldsm4t(bb2[np][0], bb2[np][1], bb2[np][2], bb2[np][3],
                       s2u(&sc[(ks + tbrow) * 40 + np * 16 + tbcol]));
            #pragma unroll
            for (int np = 0; np < 2; ++np) {
                mma_f16(c[2 * np][0], c[2 * np][1], c[2 * np][2], c[2 * np][3],
                        a[0], a[1], a[2], a[3], bb2[np][0], bb2[np][1]);
                mma_f16(c[2 * np + 1][0], c[2 * np + 1][1], c[2 * np + 1][2], c[2 * np + 1][3],
                        a[0], a[1], a[2], a[3], bb2[np][2], bb2[np][3]);
            }
        }
    }
    #undef VMMA_ISSUE
    // transpose v^T[i][n] -> v[n][i] via smem, coalesced store
    __syncthreads();
    #pragma unroll
    for (int nt = 0; nt < 4; ++nt) {
        int nc = nt * 8 + 2 * tg;
        vsm[(wi + g)     * 33 + nc]     = c[nt][0];
        vsm[(wi + g)     * 33 + nc + 1] = c[nt][1];
        vsm[(wi + g + 8) * 33 + nc]     = c[nt][2];
        vsm[(wi + g + 8) * 33 + nc + 1] = c[nt][3];
    }
    __syncthreads();
    {
        int n = t >> 3, igrp = t & 7;
        float* vb = g_v + ((size_t)b * NCAP + n) * DIN + i0;
        #pragma unroll
        for (int q = 0; q < 4; ++q) {
            int i4 = igrp * 4 + q * 32;
            float4 o = make_float4(vsm[(i4 + 0) * 33 + n], vsm[(i4 + 1) * 33 + n],
                                   vsm[(i4 + 2) * 33 + n], vsm[(i4 + 3) * 33 + n]);
            *(float4*)(vb + i4) = o;
        }
    }
}

// ---------------- launch ----------------
extern "C" void kernel_launch(void* const* d_in, const int* in_sizes, int n_in,
                              void* d_out, int out_size) {
    const float* U = (const float*)d_in[0];   // (64, 512, 512)
    const float* W = (const float*)d_in[1];   // (512, 2048)
    float* out = (float*)d_out;               // (64, 32, 64)

    cudaFuncSetAttribute(blogmma_k, cudaFuncAttributeMaxDynamicSharedMemorySize, 38400);
    cudaFuncSetAttribute(vmma_k,    cudaFuncAttributeMaxDynamicSharedMemorySize, 33792);

    prep_k<<<512, 256>>>(U, W);
    outw_k<<<dim3(32, 8), 512>>>(out, 1, 1);                   // iteration 0 + w0
    for (int it = 0; it < 2; ++it) {
        blogmma_k<<<dim3(4, 64), 256, 38400>>>();
        vmma_k<<<dim3(4, 64), 256, 33792>>>();
        outw_k<<<dim3(32, 8), 512>>>(out, 0, it == 0);         // out + (w for iter 1 only)
    }
}

// round 17
// speedup vs baseline: 1.1349x; 1.0133x over previous
#include <cuda_runtime.h>
#include <cuda_fp16.h>
#include <cstdint>

#define B_    64
#define S_    512
#define DIN   512
#define NCAP  32
#define DCAP  64
#define EPSQ  1e-7f

// ---------------- scratch (device globals; no allocations) ----------------
__device__ __half g_Uh[B_ * S_ * DIN];         // fp16 copy of U (converted once) ~34MB
__device__ float  g_Wt[NCAP * DCAP * DIN];     // W transposed: [n][d][i]
__device__ float  g_tp[4 * B_ * DIN];          // partial column sums of U
__device__ __half g_wh[B_ * DIN * NCAP];       // w[b][i][n] fp16
__device__ __half g_ch[B_ * S_ * NCAP];        // c[b][s][n] fp16 (post-softmax)
__device__ float  g_v[B_ * NCAP * DIN];        // v[b][n][i]

// ---------------- mma / ldmatrix / cp.async helpers ----------------
__device__ __forceinline__ void mma_f16(float& c0, float& c1, float& c2, float& c3,
                                        uint32_t a0, uint32_t a1, uint32_t a2, uint32_t a3,
                                        uint32_t b0, uint32_t b1) {
    asm("mma.sync.aligned.m16n8k16.row.col.f32.f16.f16.f32 "
        "{%0,%1,%2,%3}, {%4,%5,%6,%7}, {%8,%9}, {%0,%1,%2,%3};"
        : "+f"(c0), "+f"(c1), "+f"(c2), "+f"(c3)
        : "r"(a0), "r"(a1), "r"(a2), "r"(a3), "r"(b0), "r"(b1));
}
__device__ __forceinline__ uint32_t s2u(const void* p) {
    return (uint32_t)__cvta_generic_to_shared(p);
}
__device__ __forceinline__ void ldsm4(uint32_t& r0, uint32_t& r1, uint32_t& r2, uint32_t& r3,
                                      uint32_t addr) {
    asm volatile("ldmatrix.sync.aligned.m8n8.x4.shared.b16 {%0,%1,%2,%3}, [%4];"
                 : "=r"(r0), "=r"(r1), "=r"(r2), "=r"(r3) : "r"(addr));
}
__device__ __forceinline__ void ldsm4t(uint32_t& r0, uint32_t& r1, uint32_t& r2, uint32_t& r3,
                                       uint32_t addr) {
    asm volatile("ldmatrix.sync.aligned.m8n8.x4.trans.shared.b16 {%0,%1,%2,%3}, [%4];"
                 : "=r"(r0), "=r"(r1), "=r"(r2), "=r"(r3) : "r"(addr));
}
__device__ __forceinline__ void cp16(uint32_t dst, const void* src) {
    asm volatile("cp.async.cg.shared.global [%0], [%1], 16;" :: "r"(dst), "l"(src));
}
__device__ __forceinline__ void cp_commit() {
    asm volatile("cp.async.commit_group;");
}
template <int N>
__device__ __forceinline__ void cp_wait() {
    asm volatile("cp.async.wait_group %0;" :: "n"(N));
}

// ---------------- prep: blocks 0..255 transpose W; 256..511 colsum U + fp16 convert ----
__global__ __launch_bounds__(256) void prep_k(const float* __restrict__ U,
                                              const float* __restrict__ W) {
    int t = threadIdx.x;
    if (blockIdx.x < 256) {
        int n  = blockIdx.x >> 3;
        int i0 = (blockIdx.x & 7) * 64;
        __shared__ float sm[64 * 65];
        #pragma unroll
        for (int r = 0; r < 16; ++r) {
            int idx = r * 256 + t;
            int d = idx & 63, ii = idx >> 6;
            sm[d * 65 + ii] = W[(size_t)(i0 + ii) * 2048 + n * 64 + d];
        }
        __syncthreads();
        #pragma unroll
        for (int r = 0; r < 16; ++r) {
            int idx = r * 256 + t;
            int ii = idx & 63, d = idx >> 6;
            g_Wt[((size_t)n * 64 + d) * 512 + i0 + ii] = sm[d * 65 + ii];
        }
    } else {
        int idx = blockIdx.x - 256;
        int b = idx & 63, sc = idx >> 6;
        size_t base = ((size_t)b * S_ + sc * 128) * DIN;
        const float2* p = (const float2*)(U + base) + t;
        __half2* qh = (__half2*)(g_Uh + base) + t;
        float2 a = make_float2(0.f, 0.f);
        #pragma unroll 4
        for (int s = 0; s < 128; ++s) {
            float2 f = p[(size_t)s * 256];
            a.x += f.x; a.y += f.y;
            qh[(size_t)s * 256] = __floats2half2_rn(f.x, f.y);
        }
        *(float2*)(g_tp + ((size_t)sc * B_ + b) * DIN + t * 2) = a;
    }
}

// ---------------- fused out + w (fp32 compute; w stored fp16) ----------------
__global__ __launch_bounds__(512) void outw_k(float* __restrict__ out, int bcast, int dow) {
    int n  = blockIdx.x;
    int b0 = blockIdx.y * 8;
    __shared__ __align__(16) float sv[8][DIN];
    __shared__ float so[8][DCAP];
    int t = threadIdx.x, w = t >> 5, lane = t & 31;
    const float* Wn = g_Wt + (size_t)n * DCAP * DIN;

    #pragma unroll
    for (int r = 0; r < 8; ++r) {
        int idx = r * 512 + t;
        int bb = idx >> 9, pos = idx & 511;
        int b = b0 + bb;
        float val;
        if (bcast)
            val = g_tp[(size_t)b * DIN + pos]
                + g_tp[((size_t)B_ + b) * DIN + pos]
                + g_tp[((size_t)2 * B_ + b) * DIN + pos]
                + g_tp[((size_t)3 * B_ + b) * DIN + pos];
        else
            val = g_v[((size_t)b * NCAP + n) * DIN + pos];
        sv[bb][pos] = val;
    }
    __syncthreads();

    #pragma unroll
    for (int r = 0; r < 4; ++r) {
        int d = r * 16 + w;
        const float4* wp = (const float4*)(Wn + (size_t)d * DIN);
        float acc[8] = {};
        #pragma unroll
        for (int q = 0; q < 4; ++q) {
            float4 wv = wp[lane + q * 32];
            #pragma unroll
            for (int bb = 0; bb < 8; ++bb) {
                float4 vv = ((const float4*)sv[bb])[lane + q * 32];
                acc[bb] += wv.x * vv.x + wv.y * vv.y + wv.z * vv.z + wv.w * vv.w;
            }
        }
        #pragma unroll
        for (int bb = 0; bb < 8; ++bb) {
            #pragma unroll
            for (int off = 16; off; off >>= 1)
                acc[bb] += __shfl_xor_sync(0xffffffffu, acc[bb], off);
        }
        if (lane == 0) {
            #pragma unroll
            for (int bb = 0; bb < 8; ++bb) so[bb][d] = acc[bb];
        }
    }
    __syncthreads();

    if (w < 8) {
        int b = b0 + w;
        float o1 = so[w][lane], o2 = so[w][lane + 32];
        if (bcast) { o1 *= (1.f / 32.f); o2 *= (1.f / 32.f); }
        float sq = o1 * o1 + o2 * o2;
        #pragma unroll
        for (int off = 16; off; off >>= 1) sq += __shfl_xor_sync(0xffffffffu, sq, off);
        float rn = rsqrtf(sq + EPSQ);
        o1 *= rn; o2 *= rn;
        out[((size_t)b * NCAP + n) * DCAP + lane]      = o1;
        out[((size_t)b * NCAP + n) * DCAP + lane + 32] = o2;
        so[w][lane]      = o1;
        so[w][lane + 32] = o2;
    }
    __syncthreads();

    if (dow) {
        int i = t;
        float acc[8] = {};
        #pragma unroll 8
        for (int d = 0; d < DCAP; ++d) {
            float wt = Wn[(size_t)d * DIN + i];
            #pragma unroll
            for (int bb = 0; bb < 8; ++bb) acc[bb] += so[bb][d] * wt;
        }
        #pragma unroll
        for (int bb = 0; bb < 8; ++bb)
            g_wh[((size_t)(b0 + bb) * DIN + i) * NCAP + n] = __float2half_rn(acc[bb]);
    }
}

// ---------------- fp16 MMA: logits[s,n] = U[s,:]·w[:,n], softmax fused ----------------
// grid (8 s-tiles, 64 b) = 512 blocks, 128 thr (4 warps). Tile 64s x 32n; warp = 16s x 32n.
// cp.async 4-stage ring (3 chunks in flight), one syncthreads per 32-k chunk.
// dyn smem: su 4 x 64x40 halfs (20480B), sw 4 x 32x40 halfs (10240B) = 30720B.
__global__ __launch_bounds__(128) void blogmma_k() {
    extern __shared__ __align__(16) char dsm[];
    __half* suB = (__half*)dsm;                    // buf stride 2560 halfs
    __half* swB = (__half*)(dsm + 20480);          // buf stride 1280 halfs
    int t = threadIdx.x, w = t >> 5, lane = t & 31;
    int g = lane >> 2, tg = lane & 3;
    int wrow = w * 16;
    int s0 = blockIdx.x * 64;
    int b  = blockIdx.y;
    const __half* Ub  = g_Uh + ((size_t)b * S_ + s0) * DIN;
    const __half* whb = g_wh + (size_t)b * DIN * NCAP;
    int arow = (lane & 7) + ((lane >> 3) & 1) * 8, acol = (lane >> 4) * 8;
    int brow = arow, bcol = acol;
    // loader coords: su 64 rows x 32 halfs (rows ur, ur+32); sw 32 rows x 32 halfs
    int ur = t >> 2, uq = t & 3;
    int wr = t >> 2, wq = t & 3;

    #define BLOG_ISSUE(CH) do {                                                   \
        int _k0 = (CH) * 32;                                                      \
        __half* _sd = suB + ((CH) & 3) * 2560;                                    \
        cp16(s2u(&_sd[ur * 40 + uq * 8]), Ub + (size_t)ur * DIN + _k0 + uq * 8);  \
        cp16(s2u(&_sd[(ur + 32) * 40 + uq * 8]),                                  \
             Ub + (size_t)(ur + 32) * DIN + _k0 + uq * 8);                        \
        __half* _sw = swB + ((CH) & 3) * 1280;                                    \
        cp16(s2u(&_sw[wr * 40 + wq * 8]),                                         \
             whb + (size_t)(_k0 + wr) * NCAP + wq * 8);                           \
        cp_commit();                                                              \
    } while (0)

    BLOG_ISSUE(0);
    BLOG_ISSUE(1);
    BLOG_ISSUE(2);

    float c[4][4] = {};
    #pragma unroll 1
    for (int ch = 0; ch < 16; ++ch) {
        if (ch <= 13) cp_wait<2>(); else if (ch == 14) cp_wait<1>(); else cp_wait<0>();
        __syncthreads();
        if (ch < 13) BLOG_ISSUE(ch + 3);
        __half* sa = suB + (ch & 3) * 2560;
        __half* sw = swB + (ch & 3) * 1280;
        #pragma unroll
        for (int ks = 0; ks < 32; ks += 16) {
            uint32_t a[4], bb2[2][4];
            ldsm4(a[0], a[1], a[2], a[3], s2u(&sa[(wrow + arow) * 40 + ks + acol]));
            #pragma unroll
            for (int np = 0; np < 2; ++np)
                ldsm4t(bb2[np][0], bb2[np][1], bb2[np][2], bb2[np][3],
                       s2u(&sw[(ks + brow) * 40 + np * 16 + bcol]));
            #pragma unroll
            for (int np = 0; np < 2; ++np) {
                mma_f16(c[2 * np][0], c[2 * np][1], c[2 * np][2], c[2 * np][3],
                        a[0], a[1], a[2], a[3], bb2[np][0], bb2[np][1]);
                mma_f16(c[2 * np + 1][0], c[2 * np + 1][1], c[2 * np + 1][2], c[2 * np + 1][3],
                        a[0], a[1], a[2], a[3], bb2[np][2], bb2[np][3]);
            }
        }
    }
    #undef BLOG_ISSUE
    // softmax over n per s-row (row's 32 n on 4 lanes sharing g: xor 1,2); fp16 store
    __half* cbase = g_ch + ((size_t)b * S_ + s0) * NCAP;
    #pragma unroll
    for (int half = 0; half < 2; ++half) {
        int row = wrow + g + half * 8;
        float v0 = c[0][half * 2], v1 = c[0][half * 2 + 1];
        float v2 = c[1][half * 2], v3 = c[1][half * 2 + 1];
        float v4 = c[2][half * 2], v5 = c[2][half * 2 + 1];
        float v6 = c[3][half * 2], v7 = c[3][half * 2 + 1];
        float m = fmaxf(fmaxf(fmaxf(v0, v1), fmaxf(v2, v3)),
                        fmaxf(fmaxf(v4, v5), fmaxf(v6, v7)));
        m = fmaxf(m, __shfl_xor_sync(0xffffffffu, m, 1));
        m = fmaxf(m, __shfl_xor_sync(0xffffffffu, m, 2));
        float e0 = __expf(v0 - m), e1 = __expf(v1 - m), e2 = __expf(v2 - m), e3 = __expf(v3 - m);
        float e4 = __expf(v4 - m), e5 = __expf(v5 - m), e6 = __expf(v6 - m), e7 = __expf(v7 - m);
        float sm = e0 + e1 + e2 + e3 + e4 + e5 + e6 + e7;
        sm += __shfl_xor_sync(0xffffffffu, sm, 1);
        sm += __shfl_xor_sync(0xffffffffu, sm, 2);
        float inv = 1.f / sm;
        __half2* cr = (__half2*)(cbase + (size_t)row * NCAP + 2 * tg);
        cr[0]  = __floats2half2_rn(e0 * inv, e1 * inv);
        cr[4]  = __floats2half2_rn(e2 * inv, e3 * inv);
        cr[8]  = __floats2half2_rn(e4 * inv, e5 * inv);
        cr[12] = __floats2half2_rn(e6 * inv, e7 * inv);
    }
}

// ---------------- fp16 MMA: v[n,i] = sum_s c[s,n] U[s,i] (v^T then transpose) ----------
// grid (8 i-tiles, 64 b) = 512 blocks, 128 thr (4 warps). Tile 64i x 32n; warp = 16i x 32n.
// cp.async 4-stage ring, one syncthreads per 32-s chunk.
// dyn smem: su 4 x 32x72 halfs (18432B), sc 4 x 32x40 halfs (10240B) = 28672B.
// Epilogue reuses [0, 8448) as vsm 64x33 floats.
__global__ __launch_bounds__(128) void vmma_k() {
    extern __shared__ __align__(16) char dsm[];
    __half* suB = (__half*)dsm;                    // buf stride 2304 halfs
    __half* scB = (__half*)(dsm + 18432);          // buf stride 1280 halfs
    float*  vsm = (float*)dsm;
    int t = threadIdx.x, w = t >> 5, lane = t & 31;
    int g = lane >> 2, tg = lane & 3;
    int wi = w * 16;
    int i0 = blockIdx.x * 64;
    int b  = blockIdx.y;
    const __half* Ub = g_Uh + (size_t)b * S_ * DIN;
    const __half* cb = g_ch + (size_t)b * S_ * NCAP;
    int tarow = (lane & 7) + ((lane >> 4) & 1) * 8, tacol = ((lane >> 3) & 1) * 8;
    int tbrow = (lane & 7) + ((lane >> 3) & 1) * 8, tbcol = (lane >> 4) * 8;
    // loader coords: su 32 rows x 64 halfs (rows ur, ur+16); sc 32 rows x 32 halfs
    int ur = t >> 3, uq = t & 7;
    int cr_ = t >> 2, cq = t & 3;

    #define VMMA_ISSUE(CH) do {                                                    \
        int _s1 = (CH) * 32;                                                       \
        __half* _sd = suB + ((CH) & 3) * 2304;                                     \
        cp16(s2u(&_sd[ur * 72 + uq * 8]),                                          \
             Ub + (size_t)(_s1 + ur) * DIN + i0 + uq * 8);                         \
        cp16(s2u(&_sd[(ur + 16) * 72 + uq * 8]),                                   \
             Ub + (size_t)(_s1 + ur + 16) * DIN + i0 + uq * 8);                    \
        __half* _sc = scB + ((CH) & 3) * 1280;                                     \
        cp16(s2u(&_sc[cr_ * 40 + cq * 8]),                                         \
             cb + (size_t)(_s1 + cr_) * NCAP + cq * 8);                            \
        cp_commit();                                                               \
    } while (0)

    VMMA_ISSUE(0);
    VMMA_ISSUE(1);
    VMMA_ISSUE(2);

    float c[4][4] = {};
    #pragma unroll 1
    for (int ch = 0; ch < 16; ++ch) {
        if (ch <= 13) cp_wait<2>(); else if (ch == 14) cp_wait<1>(); else cp_wait<0>();
        __syncthreads();
        if (ch < 13) VMMA_ISSUE(ch + 3);
        __half* sa = suB + (ch & 3) * 2304;
        __half* sc = scB + (ch & 3) * 1280;
        #pragma unroll
        for (int ks = 0; ks < 32; ks += 16) {
            uint32_t a[4], bb2[2][4];
            ldsm4t(a[0], a[1], a[2], a[3],
                   s2u(&sa[(ks + tarow) * 72 + wi + tacol]));
            #pragma unroll
            for (int np = 0; np < 2; ++np)
                ldsm4t(bb2[np][0], bb2[np][1], bb2[np][2], bb2[np][3],
                       s2u(&sc[(ks + tbrow) * 40 + np * 16 + tbcol]));
            #pragma unroll
            for (int np = 0; np < 2; ++np) {
                mma_f16(c[2 * np][0], c[2 * np][1], c[2 * np][2], c[2 * np][3],
                        a[0], a[1], a[2], a[3], bb2[np][0], bb2[np][1]);
                mma_f16(c[2 * np + 1][0], c[2 * np + 1][1], c[2 * np + 1][2], c[2 * np + 1][3],
                        a[0], a[1], a[2], a[3], bb2[np][2], bb2[np][3]);
            }
        }
    }
    #undef VMMA_ISSUE
    // transpose v^T[i][n] -> v[n][i] via smem, coalesced store
    __syncthreads();
    #pragma unroll
    for (int nt = 0; nt < 4; ++nt) {
        int nc = nt * 8 + 2 * tg;
        vsm[(wi + g)     * 33 + nc]     = c[nt][0];
        vsm[(wi + g)     * 33 + nc + 1] = c[nt][1];
        vsm[(wi + g + 8) * 33 + nc]     = c[nt][2];
        vsm[(wi + g + 8) * 33 + nc + 1] = c[nt][3];
    }
    __syncthreads();
    {
        int n = t >> 2, igrp = t & 3;
        float* vb = g_v + ((size_t)b * NCAP + n) * DIN + i0;
        #pragma unroll
        for (int q = 0; q < 4; ++q) {
            int i4 = igrp * 4 + q * 16;
            float4 o = make_float4(vsm[(i4 + 0) * 33 + n], vsm[(i4 + 1) * 33 + n],
                                   vsm[(i4 + 2) * 33 + n], vsm[(i4 + 3) * 33 + n]);
            *(float4*)(vb + i4) = o;
        }
    }
}

// ---------------- launch ----------------
extern "C" void kernel_launch(void* const* d_in, const int* in_sizes, int n_in,
                              void* d_out, int out_size) {
    const float* U = (const float*)d_in[0];   // (64, 512, 512)
    const float* W = (const float*)d_in[1];   // (512, 2048)
    float* out = (float*)d_out;               // (64, 32, 64)

    cudaFuncSetAttribute(blogmma_k, cudaFuncAttributeMaxDynamicSharedMemorySize, 30720);
    cudaFuncSetAttribute(vmma_k,    cudaFuncAttributeMaxDynamicSharedMemorySize, 28672);

    prep_k<<<512, 256>>>(U, W);
    outw_k<<<dim3(32, 8), 512>>>(out, 1, 1);                   // iteration 0 + w0
    for (int it = 0; it < 2; ++it) {
        blogmma_k<<<dim3(8, 64), 128, 30720>>>();
        vmma_k<<<dim3(8, 64), 128, 28672>>>();
        outw_k<<<dim3(32, 8), 512>>>(out, 0, it == 0);         // out + (w for iter 1 only)
    }
}